// round 15
// baseline (speedup 1.0000x reference)
#include <cuda_runtime.h>
#include <cuda_bf16.h>
#include <cstdint>

// Problem constants: N=50000, E=600000, D=128, NF=3, V=8
#define D_DIM 128
#define NF_DIM 3
#define V_DIM 8
#define MAX_N 50048
#define MAX_E 600064
#define SBW 68  // 32-bit words per smem row (136 bf16)

// Scratch (device globals; no allocation allowed)
__device__ float g_acc[MAX_N * D_DIM];          // neighbor message sums
__device__ float g_deg[MAX_N];                  // in-degree -> (after invd) 1/(deg+1)
__device__ uint32_t g_Wpk[2 * D_DIM * SBW];     // packed W: [Wth | Wtl], smem-ready
__device__ float g_etab[512 * D_DIM];           // all 512 edge-feature sum combos
__device__ int   g_combo[MAX_E];                // per-edge combo index

// ---------------------------------------------------------------------------
// K0 (prep): W packing (blocks 0..31) + combo table (blocks 32..287, 2/block)
//            + eidx->combo combine (all blocks, grid-stride).
// ---------------------------------------------------------------------------
__global__ void prep_kernel(const float* __restrict__ W,
                            const float* __restrict__ emb,
                            const int* __restrict__ eidx, int E) {
    int bid = blockIdx.x;
    int tid = threadIdx.x;

    // --- W packing: 32 blocks x 256 threads = 8192 (n, kpair) items ---
    if (bid < 32) {
        int i = bid * 256 + tid;
        int n = i >> 6;
        int kp = i & 63;
        int k = kp * 2;
        float x0 = __ldg(W + k * D_DIM + n);
        float x1 = __ldg(W + (k + 1) * D_DIM + n);
        __nv_bfloat16 h0 = __float2bfloat16_rn(x0);
        __nv_bfloat16 h1 = __float2bfloat16_rn(x1);
        __nv_bfloat16 l0 = __float2bfloat16_rn(x0 - __bfloat162float(h0));
        __nv_bfloat16 l1 = __float2bfloat16_rn(x1 - __bfloat162float(h1));
        __nv_bfloat162 hp = __nv_bfloat162(h0, h1);
        __nv_bfloat162 lp = __nv_bfloat162(l0, l1);
        g_Wpk[n * SBW + kp]               = *reinterpret_cast<uint32_t*>(&hp);
        g_Wpk[D_DIM * SBW + n * SBW + kp] = *reinterpret_cast<uint32_t*>(&lp);
    } else if (bid < 288) {
        // --- Combo table: 256 blocks x 2 combos; 128 threads per combo ---
        int combo = (bid - 32) * 2 + (tid >> 7);
        int dim = tid & 127;
        int i0 = combo & 7;
        int i1 = (combo >> 3) & 7;
        int i2 = combo >> 6;
        float s = __ldg(emb + i0 * D_DIM + dim) +
                  __ldg(emb + (V_DIM + i1) * D_DIM + dim) +
                  __ldg(emb + (2 * V_DIM + i2) * D_DIM + dim);
        g_etab[combo * D_DIM + dim] = s;
    }

    // --- eidx combine: grid-stride over E ---
    for (int e = bid * blockDim.x + tid; e < E; e += gridDim.x * blockDim.x) {
        int i0 = __ldg(eidx + e * NF_DIM + 0);
        int i1 = __ldg(eidx + e * NF_DIM + 1);
        int i2 = __ldg(eidx + e * NF_DIM + 2);
        g_combo[e] = i0 + (i1 << 3) + (i2 << 6);
    }
}

// ---------------------------------------------------------------------------
// K1: edge scatter. One edge per warp; lane owns 4 contiguous dims.
//     Lean form: 2 vector gathers (nfeat[src], etab[combo]) + 1 RED.
// ---------------------------------------------------------------------------
__global__ void edge_scatter_kernel(const float* __restrict__ nfeat,
                                    const int* __restrict__ src,
                                    const int* __restrict__ dst,
                                    int E) {
    int e = blockIdx.x * (blockDim.x >> 5) + (threadIdx.x >> 5);
    if (e >= E) return;
    int lane = threadIdx.x & 31;

    int s  = __ldg(src + e);
    int d  = __ldg(dst + e);
    int cb = __ldg(g_combo + e);

    const float4* nf4 = reinterpret_cast<const float4*>(nfeat);
    const float4* et4 = reinterpret_cast<const float4*>(g_etab);

    float4 v = __ldg(nf4 + (size_t)s * 32 + lane);
    float4 t = et4[cb * 32 + lane];

    float mx = v.x + t.x;
    float my = v.y + t.y;
    float mz = v.z + t.z;
    float mw = v.w + t.w;

    float* p = g_acc + (size_t)d * D_DIM + lane * 4;
    asm volatile("red.global.add.v4.f32 [%0], {%1, %2, %3, %4};"
                 :: "l"(p), "f"(mx), "f"(my), "f"(mz), "f"(mw) : "memory");

    if (lane == 0) {
        atomicAdd(&g_deg[d], 1.0f);
    }
}

// ---------------------------------------------------------------------------
// K1b: g_deg[i] -> 1/(g_deg[i]+1)
// ---------------------------------------------------------------------------
__global__ void invd_kernel(int N) {
    int i = blockIdx.x * blockDim.x + threadIdx.x;
    if (i < N) g_deg[i] = 1.0f / (g_deg[i] + 1.0f);
}

// ---------------------------------------------------------------------------
// K2: PERSISTENT PIPELINED bf16x3 GEMM. grid=148 x 512 (16 warps, 1 CTA/SM).
//     64-row tiles, double-buffered H smem, register prefetch of next tile.
//     out = ((nfeat + g_acc) * g_deg) @ W + b      (g_deg pre-inverted)
// ---------------------------------------------------------------------------
#define HBUF_WORDS (64 * SBW)

__global__ void __launch_bounds__(512, 1)
gemm_bf16_kernel(const float* __restrict__ nfeat,
                 const float* __restrict__ b,
                 float* __restrict__ out, int N, int numTiles) {
    extern __shared__ uint32_t smu[];
    uint32_t* Wth = smu;                        // 128*68
    uint32_t* Wtl = Wth + D_DIM * SBW;          // 128*68
    uint32_t* Hbuf = Wtl + D_DIM * SBW;         // 4 * 64*68
    float* bs = reinterpret_cast<float*>(Hbuf + 4 * HBUF_WORDS);  // 128

    int tid = threadIdx.x;

    // Prologue: stage packed W (pure uint4 copy) + bias
    {
        const uint4* src4 = reinterpret_cast<const uint4*>(g_Wpk);
        uint4* dst4 = reinterpret_cast<uint4*>(smu);
        #pragma unroll
        for (int i = tid; i < (2 * D_DIM * SBW) / 4; i += 512)
            dst4[i] = src4[i];
        if (tid < D_DIM) bs[tid] = __ldg(b + tid);
    }

    // Staging geometry: row = tid>>3, q = tid&7; thread covers float4 cols q*4..q*4+3.
    int srow = tid >> 3;
    int q = tid & 7;
    const float4* nf4 = reinterpret_cast<const float4*>(nfeat);
    const float4* ac4 = reinterpret_cast<const float4*>(g_acc);

    int wid = tid >> 5;
    int lane = tid & 31;
    int gid = lane >> 2;
    int tig = lane & 3;
    int wr = (wid >> 2) * 16;   // warp grid 4x4; warp tile 16 rows x 32 cols
    int wc = (wid & 3) * 32;

    int tile = blockIdx.x;

    // Prefetch first tile into registers (pinvd = plain load, no math in chain)
    float4 pn[4], pa[4];
    float pinvd = 0.f;
    {
        int row = tile * 64 + srow;
        bool ok = (row < N);
        pinvd = ok ? g_deg[row] : 0.f;
        #pragma unroll
        for (int j = 0; j < 4; j++) {
            pn[j] = ok ? __ldg(nf4 + (size_t)row * 32 + q * 4 + j)
                       : make_float4(0.f, 0.f, 0.f, 0.f);
            pa[j] = ok ? *(ac4 + (size_t)row * 32 + q * 4 + j)
                       : make_float4(0.f, 0.f, 0.f, 0.f);
        }
    }

    int cur = 0;
    while (tile < numTiles) {
        int row0 = tile * 64;
        uint32_t* Hh = Hbuf + cur * (2 * HBUF_WORDS);
        uint32_t* Hl = Hh + HBUF_WORDS;

        // Convert prefetched registers -> smem (truncation hi split + bf16 lo)
        {
            #pragma unroll
            for (int j = 0; j < 4; j++) {
                float x0 = (pn[j].x + pa[j].x) * pinvd;
                float x1 = (pn[j].y + pa[j].y) * pinvd;
                float x2 = (pn[j].z + pa[j].z) * pinvd;
                float x3 = (pn[j].w + pa[j].w) * pinvd;
                uint32_t b0 = __float_as_uint(x0), b1 = __float_as_uint(x1);
                uint32_t b2 = __float_as_uint(x2), b3 = __float_as_uint(x3);
                uint32_t hp0, hp1;
                asm("prmt.b32 %0, %1, %2, 0x7632;" : "=r"(hp0) : "r"(b0), "r"(b1));
                asm("prmt.b32 %0, %1, %2, 0x7632;" : "=r"(hp1) : "r"(b2), "r"(b3));
                float l0 = x0 - __uint_as_float(b0 & 0xFFFF0000u);
                float l1 = x1 - __uint_as_float(b1 & 0xFFFF0000u);
                float l2 = x2 - __uint_as_float(b2 & 0xFFFF0000u);
                float l3 = x3 - __uint_as_float(b3 & 0xFFFF0000u);
                __nv_bfloat162 lp0 = __floats2bfloat162_rn(l0, l1);
                __nv_bfloat162 lp1 = __floats2bfloat162_rn(l2, l3);
                int base = srow * SBW + (q * 4 + j) * 2;
                Hh[base]     = hp0;
                Hh[base + 1] = hp1;
                Hl[base]     = *reinterpret_cast<uint32_t*>(&lp0);
                Hl[base + 1] = *reinterpret_cast<uint32_t*>(&lp1);
            }
        }
        __syncthreads();

        // Issue prefetch for next tile (latency hides under mainloop)
        int ntile = tile + gridDim.x;
        if (ntile < numTiles) {
            int row = ntile * 64 + srow;
            bool ok = (row < N);
            pinvd = ok ? g_deg[row] : 0.f;
            #pragma unroll
            for (int j = 0; j < 4; j++) {
                pn[j] = ok ? __ldg(nf4 + (size_t)row * 32 + q * 4 + j)
                           : make_float4(0.f, 0.f, 0.f, 0.f);
                pa[j] = ok ? *(ac4 + (size_t)row * 32 + q * 4 + j)
                           : make_float4(0.f, 0.f, 0.f, 0.f);
            }
        }

        // Mainloop: warp tile 16 rows x 32 cols (4 n-tiles)
        float c[4][4];
        #pragma unroll
        for (int nt = 0; nt < 4; nt++)
            #pragma unroll
            for (int r = 0; r < 4; r++) c[nt][r] = 0.f;

        #pragma unroll
        for (int kw = 0; kw < 64; kw += 8) {   // K chunk = 16
            uint32_t ah[4], al[4];
            {
                int r = wr + gid;
                ah[0] = Hh[r * SBW + kw + tig];
                ah[1] = Hh[(r + 8) * SBW + kw + tig];
                ah[2] = Hh[r * SBW + kw + 4 + tig];
                ah[3] = Hh[(r + 8) * SBW + kw + 4 + tig];
                al[0] = Hl[r * SBW + kw + tig];
                al[1] = Hl[(r + 8) * SBW + kw + tig];
                al[2] = Hl[r * SBW + kw + 4 + tig];
                al[3] = Hl[(r + 8) * SBW + kw + 4 + tig];
            }
            uint32_t bh[4][2], bl[4][2];
            #pragma unroll
            for (int nt = 0; nt < 4; nt++) {
                int n = wc + nt * 8 + gid;
                bh[nt][0] = Wth[n * SBW + kw + tig];
                bh[nt][1] = Wth[n * SBW + kw + 4 + tig];
                bl[nt][0] = Wtl[n * SBW + kw + tig];
                bl[nt][1] = Wtl[n * SBW + kw + 4 + tig];
            }
            #define MMA16(CR, A, B)                                              \
                asm volatile(                                                    \
                    "mma.sync.aligned.m16n8k16.row.col.f32.bf16.bf16.f32 "       \
                    "{%0,%1,%2,%3}, {%4,%5,%6,%7}, {%8,%9}, {%0,%1,%2,%3};"      \
                    : "+f"((CR)[0]), "+f"((CR)[1]),                              \
                      "+f"((CR)[2]), "+f"((CR)[3])                               \
                    : "r"(A[0]), "r"(A[1]), "r"(A[2]), "r"(A[3]),                \
                      "r"(B[0]), "r"(B[1]))
            #pragma unroll
            for (int nt = 0; nt < 4; nt++) MMA16(c[nt], ah, bh[nt]);
            #pragma unroll
            for (int nt = 0; nt < 4; nt++) MMA16(c[nt], al, bh[nt]);
            #pragma unroll
            for (int nt = 0; nt < 4; nt++) MMA16(c[nt], ah, bl[nt]);
            #undef MMA16
        }

        // Epilogue: bias + store
        #pragma unroll
        for (int nt = 0; nt < 4; nt++) {
            int col = wc + nt * 8 + 2 * tig;
            float bx = bs[col], by = bs[col + 1];
            int r_top = row0 + wr + gid;
            if (r_top < N) {
                float2 o = make_float2(c[nt][0] + bx, c[nt][1] + by);
                *reinterpret_cast<float2*>(out + (size_t)r_top * D_DIM + col) = o;
            }
            int r_bot = r_top + 8;
            if (r_bot < N) {
                float2 o = make_float2(c[nt][2] + bx, c[nt][3] + by);
                *reinterpret_cast<float2*>(out + (size_t)r_bot * D_DIM + col) = o;
            }
        }

        tile = ntile;
        cur ^= 1;
        __syncthreads();  // buffer reads done before refill
    }
}

// ---------------------------------------------------------------------------
// Launch
// Inputs: nfeat[N*D] f32, src[E] i32, dst[E] i32, efeat_idx[E*3] i32,
//         edge_emb[3*8*128] f32, W[128*128] f32, b[128] f32 -> out float[N*128]
// ---------------------------------------------------------------------------
extern "C" void kernel_launch(void* const* d_in, const int* in_sizes, int n_in,
                              void* d_out, int out_size) {
    const float* nfeat = (const float*)d_in[0];
    const int*   src   = (const int*)d_in[1];
    const int*   dst   = (const int*)d_in[2];
    const int*   eidx  = (const int*)d_in[3];
    const float* emb   = (const float*)d_in[4];
    const float* W     = (const float*)d_in[5];
    const float* b     = (const float*)d_in[6];
    float* out = (float*)d_out;

    int N = in_sizes[0] / D_DIM;
    int E = in_sizes[1];

    // Zero accumulators (graph-capturable async memsets)
    void* acc_ptr = nullptr;
    void* deg_ptr = nullptr;
    cudaGetSymbolAddress(&acc_ptr, g_acc);
    cudaGetSymbolAddress(&deg_ptr, g_deg);
    cudaMemsetAsync(acc_ptr, 0, (size_t)N * D_DIM * sizeof(float));
    cudaMemsetAsync(deg_ptr, 0, (size_t)N * sizeof(float));

    // Prep: W pack + combo table + eidx combine
    int prep_blocks = (E + 255) / 256;
    if (prep_blocks < 288) prep_blocks = 288;
    prep_kernel<<<prep_blocks, 256>>>(W, emb, eidx, E);

    // Edge scatter (one edge per warp, lean 2-gather form)
    edge_scatter_kernel<<<(E + 7) / 8, 256>>>(nfeat, src, dst, E);

    // deg -> 1/(deg+1)
    invd_kernel<<<(N + 511) / 512, 512>>>(N);

    // Persistent pipelined GEMM
    int numTiles = (N + 63) / 64;
    int smem = (2 * D_DIM * SBW + 4 * HBUF_WORDS + 128) * 4;  // 139,776 B
    cudaFuncSetAttribute(gemm_bf16_kernel, cudaFuncAttributeMaxDynamicSharedMemorySize, smem);
    gemm_bf16_kernel<<<148, 512, smem>>>(nfeat, b, out, N, numTiles);
}

// round 16
// speedup vs baseline: 1.0048x; 1.0048x over previous
#include <cuda_runtime.h>
#include <cuda_bf16.h>
#include <cstdint>

// Problem constants: N=50000, E=600000, D=128, NF=3, V=8
#define D_DIM 128
#define NF_DIM 3
#define V_DIM 8
#define MAX_N 50048
#define SBW 68  // 32-bit words per smem row (136 bf16)

// Scratch (device globals; no allocation allowed)
__device__ float g_acc[MAX_N * D_DIM];          // neighbor message sums
__device__ float g_deg[MAX_N];                  // in-degree -> (after invd) 1/(deg+1)
__device__ uint32_t g_Wpk[2 * D_DIM * SBW];     // packed W: [Wth | Wtl], smem-ready
__device__ float g_etab[512 * D_DIM];           // all 512 edge-feature sum combos

// ---------------------------------------------------------------------------
// K0 (prep, 288 blocks): W packing (blocks 0..31) + combo table (32..287).
// ---------------------------------------------------------------------------
__global__ void prep_kernel(const float* __restrict__ W,
                            const float* __restrict__ emb) {
    int bid = blockIdx.x;
    int tid = threadIdx.x;

    if (bid < 32) {
        // --- W packing: 32 blocks x 256 threads = 8192 (n, kpair) items ---
        int i = bid * 256 + tid;
        int n = i >> 6;
        int kp = i & 63;
        int k = kp * 2;
        float x0 = __ldg(W + k * D_DIM + n);
        float x1 = __ldg(W + (k + 1) * D_DIM + n);
        __nv_bfloat16 h0 = __float2bfloat16_rn(x0);
        __nv_bfloat16 h1 = __float2bfloat16_rn(x1);
        __nv_bfloat16 l0 = __float2bfloat16_rn(x0 - __bfloat162float(h0));
        __nv_bfloat16 l1 = __float2bfloat16_rn(x1 - __bfloat162float(h1));
        __nv_bfloat162 hp = __nv_bfloat162(h0, h1);
        __nv_bfloat162 lp = __nv_bfloat162(l0, l1);
        g_Wpk[n * SBW + kp]               = *reinterpret_cast<uint32_t*>(&hp);
        g_Wpk[D_DIM * SBW + n * SBW + kp] = *reinterpret_cast<uint32_t*>(&lp);
    } else {
        // --- Combo table: 256 blocks x 2 combos; 128 threads per combo ---
        int combo = (bid - 32) * 2 + (tid >> 7);
        int dim = tid & 127;
        int i0 = combo & 7;
        int i1 = (combo >> 3) & 7;
        int i2 = combo >> 6;
        float s = __ldg(emb + i0 * D_DIM + dim) +
                  __ldg(emb + (V_DIM + i1) * D_DIM + dim) +
                  __ldg(emb + (2 * V_DIM + i2) * D_DIM + dim);
        g_etab[combo * D_DIM + dim] = s;
    }
}

// ---------------------------------------------------------------------------
// K1: edge scatter. One edge per warp; lane owns 4 contiguous dims.
//     combo computed inline from eidx (uniform scalar loads, broadcast wf).
//     2 vector gathers (nfeat[src], etab[combo]) + 1 RED.128 per edge.
// ---------------------------------------------------------------------------
__global__ void edge_scatter_kernel(const float* __restrict__ nfeat,
                                    const int* __restrict__ src,
                                    const int* __restrict__ dst,
                                    const int* __restrict__ eidx,
                                    int E) {
    int e = blockIdx.x * (blockDim.x >> 5) + (threadIdx.x >> 5);
    if (e >= E) return;
    int lane = threadIdx.x & 31;

    int s  = __ldg(src + e);
    int d  = __ldg(dst + e);
    int i0 = __ldg(eidx + e * NF_DIM + 0);
    int i1 = __ldg(eidx + e * NF_DIM + 1);
    int i2 = __ldg(eidx + e * NF_DIM + 2);
    int cb = i0 + (i1 << 3) + (i2 << 6);

    const float4* nf4 = reinterpret_cast<const float4*>(nfeat);
    const float4* et4 = reinterpret_cast<const float4*>(g_etab);

    float4 v = __ldg(nf4 + (size_t)s * 32 + lane);
    float4 t = et4[cb * 32 + lane];

    float mx = v.x + t.x;
    float my = v.y + t.y;
    float mz = v.z + t.z;
    float mw = v.w + t.w;

    float* p = g_acc + (size_t)d * D_DIM + lane * 4;
    asm volatile("red.global.add.v4.f32 [%0], {%1, %2, %3, %4};"
                 :: "l"(p), "f"(mx), "f"(my), "f"(mz), "f"(mw) : "memory");

    if (lane == 0) {
        atomicAdd(&g_deg[d], 1.0f);
    }
}

// ---------------------------------------------------------------------------
// K1b: g_deg[i] -> 1/(g_deg[i]+1)
// ---------------------------------------------------------------------------
__global__ void invd_kernel(int N) {
    int i = blockIdx.x * blockDim.x + threadIdx.x;
    if (i < N) g_deg[i] = 1.0f / (g_deg[i] + 1.0f);
}

// ---------------------------------------------------------------------------
// K2: PERSISTENT PIPELINED bf16x3 GEMM. grid=148 x 512 (16 warps, 1 CTA/SM).
//     64-row tiles, double-buffered H smem, register prefetch of next tile.
//     out = ((nfeat + g_acc) * g_deg) @ W + b      (g_deg pre-inverted)
// ---------------------------------------------------------------------------
#define HBUF_WORDS (64 * SBW)

__global__ void __launch_bounds__(512, 1)
gemm_bf16_kernel(const float* __restrict__ nfeat,
                 const float* __restrict__ b,
                 float* __restrict__ out, int N, int numTiles) {
    extern __shared__ uint32_t smu[];
    uint32_t* Wth = smu;                        // 128*68
    uint32_t* Wtl = Wth + D_DIM * SBW;          // 128*68
    uint32_t* Hbuf = Wtl + D_DIM * SBW;         // 4 * 64*68
    float* bs = reinterpret_cast<float*>(Hbuf + 4 * HBUF_WORDS);  // 128

    int tid = threadIdx.x;

    // Prologue: stage packed W (pure uint4 copy) + bias
    {
        const uint4* src4 = reinterpret_cast<const uint4*>(g_Wpk);
        uint4* dst4 = reinterpret_cast<uint4*>(smu);
        #pragma unroll
        for (int i = tid; i < (2 * D_DIM * SBW) / 4; i += 512)
            dst4[i] = src4[i];
        if (tid < D_DIM) bs[tid] = __ldg(b + tid);
    }

    // Staging geometry: row = tid>>3, q = tid&7; thread covers float4 cols q*4..q*4+3.
    int srow = tid >> 3;
    int q = tid & 7;
    const float4* nf4 = reinterpret_cast<const float4*>(nfeat);
    const float4* ac4 = reinterpret_cast<const float4*>(g_acc);

    int wid = tid >> 5;
    int lane = tid & 31;
    int gid = lane >> 2;
    int tig = lane & 3;
    int wr = (wid >> 2) * 16;   // warp grid 4x4; warp tile 16 rows x 32 cols
    int wc = (wid & 3) * 32;

    int tile = blockIdx.x;

    // Prefetch first tile into registers (pinvd = plain load, no math in chain)
    float4 pn[4], pa[4];
    float pinvd = 0.f;
    {
        int row = tile * 64 + srow;
        bool ok = (row < N);
        pinvd = ok ? g_deg[row] : 0.f;
        #pragma unroll
        for (int j = 0; j < 4; j++) {
            pn[j] = ok ? __ldg(nf4 + (size_t)row * 32 + q * 4 + j)
                       : make_float4(0.f, 0.f, 0.f, 0.f);
            pa[j] = ok ? *(ac4 + (size_t)row * 32 + q * 4 + j)
                       : make_float4(0.f, 0.f, 0.f, 0.f);
        }
    }

    int cur = 0;
    while (tile < numTiles) {
        int row0 = tile * 64;
        uint32_t* Hh = Hbuf + cur * (2 * HBUF_WORDS);
        uint32_t* Hl = Hh + HBUF_WORDS;

        // Convert prefetched registers -> smem (truncation hi split + bf16 lo)
        {
            #pragma unroll
            for (int j = 0; j < 4; j++) {
                float x0 = (pn[j].x + pa[j].x) * pinvd;
                float x1 = (pn[j].y + pa[j].y) * pinvd;
                float x2 = (pn[j].z + pa[j].z) * pinvd;
                float x3 = (pn[j].w + pa[j].w) * pinvd;
                uint32_t b0 = __float_as_uint(x0), b1 = __float_as_uint(x1);
                uint32_t b2 = __float_as_uint(x2), b3 = __float_as_uint(x3);
                uint32_t hp0, hp1;
                asm("prmt.b32 %0, %1, %2, 0x7632;" : "=r"(hp0) : "r"(b0), "r"(b1));
                asm("prmt.b32 %0, %1, %2, 0x7632;" : "=r"(hp1) : "r"(b2), "r"(b3));
                float l0 = x0 - __uint_as_float(b0 & 0xFFFF0000u);
                float l1 = x1 - __uint_as_float(b1 & 0xFFFF0000u);
                float l2 = x2 - __uint_as_float(b2 & 0xFFFF0000u);
                float l3 = x3 - __uint_as_float(b3 & 0xFFFF0000u);
                __nv_bfloat162 lp0 = __floats2bfloat162_rn(l0, l1);
                __nv_bfloat162 lp1 = __floats2bfloat162_rn(l2, l3);
                int base = srow * SBW + (q * 4 + j) * 2;
                Hh[base]     = hp0;
                Hh[base + 1] = hp1;
                Hl[base]     = *reinterpret_cast<uint32_t*>(&lp0);
                Hl[base + 1] = *reinterpret_cast<uint32_t*>(&lp1);
            }
        }
        __syncthreads();

        // Issue prefetch for next tile (latency hides under mainloop)
        int ntile = tile + gridDim.x;
        if (ntile < numTiles) {
            int row = ntile * 64 + srow;
            bool ok = (row < N);
            pinvd = ok ? g_deg[row] : 0.f;
            #pragma unroll
            for (int j = 0; j < 4; j++) {
                pn[j] = ok ? __ldg(nf4 + (size_t)row * 32 + q * 4 + j)
                           : make_float4(0.f, 0.f, 0.f, 0.f);
                pa[j] = ok ? *(ac4 + (size_t)row * 32 + q * 4 + j)
                           : make_float4(0.f, 0.f, 0.f, 0.f);
            }
        }

        // Mainloop: warp tile 16 rows x 32 cols (4 n-tiles)
        float c[4][4];
        #pragma unroll
        for (int nt = 0; nt < 4; nt++)
            #pragma unroll
            for (int r = 0; r < 4; r++) c[nt][r] = 0.f;

        #pragma unroll
        for (int kw = 0; kw < 64; kw += 8) {   // K chunk = 16
            uint32_t ah[4], al[4];
            {
                int r = wr + gid;
                ah[0] = Hh[r * SBW + kw + tig];
                ah[1] = Hh[(r + 8) * SBW + kw + tig];
                ah[2] = Hh[r * SBW + kw + 4 + tig];
                ah[3] = Hh[(r + 8) * SBW + kw + 4 + tig];
                al[0] = Hl[r * SBW + kw + tig];
                al[1] = Hl[(r + 8) * SBW + kw + tig];
                al[2] = Hl[r * SBW + kw + 4 + tig];
                al[3] = Hl[(r + 8) * SBW + kw + 4 + tig];
            }
            uint32_t bh[4][2], bl[4][2];
            #pragma unroll
            for (int nt = 0; nt < 4; nt++) {
                int n = wc + nt * 8 + gid;
                bh[nt][0] = Wth[n * SBW + kw + tig];
                bh[nt][1] = Wth[n * SBW + kw + 4 + tig];
                bl[nt][0] = Wtl[n * SBW + kw + tig];
                bl[nt][1] = Wtl[n * SBW + kw + 4 + tig];
            }
            #define MMA16(CR, A, B)                                              \
                asm volatile(                                                    \
                    "mma.sync.aligned.m16n8k16.row.col.f32.bf16.bf16.f32 "       \
                    "{%0,%1,%2,%3}, {%4,%5,%6,%7}, {%8,%9}, {%0,%1,%2,%3};"      \
                    : "+f"((CR)[0]), "+f"((CR)[1]),                              \
                      "+f"((CR)[2]), "+f"((CR)[3])                               \
                    : "r"(A[0]), "r"(A[1]), "r"(A[2]), "r"(A[3]),                \
                      "r"(B[0]), "r"(B[1]))
            #pragma unroll
            for (int nt = 0; nt < 4; nt++) MMA16(c[nt], ah, bh[nt]);
            #pragma unroll
            for (int nt = 0; nt < 4; nt++) MMA16(c[nt], al, bh[nt]);
            #pragma unroll
            for (int nt = 0; nt < 4; nt++) MMA16(c[nt], ah, bl[nt]);
            #undef MMA16
        }

        // Epilogue: bias + store
        #pragma unroll
        for (int nt = 0; nt < 4; nt++) {
            int col = wc + nt * 8 + 2 * tig;
            float bx = bs[col], by = bs[col + 1];
            int r_top = row0 + wr + gid;
            if (r_top < N) {
                float2 o = make_float2(c[nt][0] + bx, c[nt][1] + by);
                *reinterpret_cast<float2*>(out + (size_t)r_top * D_DIM + col) = o;
            }
            int r_bot = r_top + 8;
            if (r_bot < N) {
                float2 o = make_float2(c[nt][2] + bx, c[nt][3] + by);
                *reinterpret_cast<float2*>(out + (size_t)r_bot * D_DIM + col) = o;
            }
        }

        tile = ntile;
        cur ^= 1;
        __syncthreads();  // buffer reads done before refill
    }
}

// ---------------------------------------------------------------------------
// Launch
// Inputs: nfeat[N*D] f32, src[E] i32, dst[E] i32, efeat_idx[E*3] i32,
//         edge_emb[3*8*128] f32, W[128*128] f32, b[128] f32 -> out float[N*128]
// ---------------------------------------------------------------------------
extern "C" void kernel_launch(void* const* d_in, const int* in_sizes, int n_in,
                              void* d_out, int out_size) {
    const float* nfeat = (const float*)d_in[0];
    const int*   src   = (const int*)d_in[1];
    const int*   dst   = (const int*)d_in[2];
    const int*   eidx  = (const int*)d_in[3];
    const float* emb   = (const float*)d_in[4];
    const float* W     = (const float*)d_in[5];
    const float* b     = (const float*)d_in[6];
    float* out = (float*)d_out;

    int N = in_sizes[0] / D_DIM;
    int E = in_sizes[1];

    // Zero accumulators (graph-capturable async memsets)
    void* acc_ptr = nullptr;
    void* deg_ptr = nullptr;
    cudaGetSymbolAddress(&acc_ptr, g_acc);
    cudaGetSymbolAddress(&deg_ptr, g_deg);
    cudaMemsetAsync(acc_ptr, 0, (size_t)N * D_DIM * sizeof(float));
    cudaMemsetAsync(deg_ptr, 0, (size_t)N * sizeof(float));

    // Prep: W pack + combo table (tiny, 288 blocks)
    prep_kernel<<<288, 256>>>(W, emb);

    // Edge scatter (one edge per warp, inline combo, 2 gathers + RED)
    edge_scatter_kernel<<<(E + 7) / 8, 256>>>(nfeat, src, dst, eidx, E);

    // deg -> 1/(deg+1)
    invd_kernel<<<(N + 511) / 512, 512>>>(N);

    // Persistent pipelined GEMM
    int numTiles = (N + 63) / 64;
    int smem = (2 * D_DIM * SBW + 4 * HBUF_WORDS + 128) * 4;  // 139,776 B
    cudaFuncSetAttribute(gemm_bf16_kernel, cudaFuncAttributeMaxDynamicSharedMemorySize, smem);
    gemm_bf16_kernel<<<148, 512, smem>>>(nfeat, b, out, N, numTiles);
}

// round 17
// speedup vs baseline: 1.0660x; 1.0609x over previous
#include <cuda_runtime.h>
#include <cuda_bf16.h>
#include <cstdint>

// Problem constants: N=50000, E=600000, D=128, NF=3, V=8
#define D_DIM 128
#define NF_DIM 3
#define V_DIM 8
#define MAX_N 50048
#define SBW 68  // 32-bit words per smem row (136 bf16)

// Scratch (device globals; no allocation allowed)
__device__ float g_acc[MAX_N * D_DIM];          // seeded with nfeat, then message sums
__device__ float g_deg[MAX_N];                  // in-degree -> (after invd) 1/(deg+1)
__device__ uint32_t g_Wpk[2 * D_DIM * SBW];     // packed W: [Wth | Wtl], smem-ready

// ---------------------------------------------------------------------------
// K1: edge scatter (one edge per warp) + W packing folded into first 32 blocks.
//     emb table is 12KB -> L1-resident, gathers are L1 hits.
// ---------------------------------------------------------------------------
__global__ void edge_scatter_kernel(const float* __restrict__ nfeat,
                                    const int* __restrict__ src,
                                    const int* __restrict__ dst,
                                    const int* __restrict__ eidx,
                                    const float* __restrict__ emb,
                                    const float* __restrict__ W,
                                    int E) {
    // --- Folded W packing: first 32 blocks x 256 threads cover 8192 items ---
    if (blockIdx.x < 32) {
        int i = blockIdx.x * 256 + threadIdx.x;   // (n, kpair)
        int n = i >> 6;
        int kp = i & 63;
        int k = kp * 2;
        float x0 = __ldg(W + k * D_DIM + n);
        float x1 = __ldg(W + (k + 1) * D_DIM + n);
        __nv_bfloat16 h0 = __float2bfloat16_rn(x0);
        __nv_bfloat16 h1 = __float2bfloat16_rn(x1);
        __nv_bfloat16 l0 = __float2bfloat16_rn(x0 - __bfloat162float(h0));
        __nv_bfloat16 l1 = __float2bfloat16_rn(x1 - __bfloat162float(h1));
        __nv_bfloat162 hp = __nv_bfloat162(h0, h1);
        __nv_bfloat162 lp = __nv_bfloat162(l0, l1);
        g_Wpk[n * SBW + kp]               = *reinterpret_cast<uint32_t*>(&hp);
        g_Wpk[D_DIM * SBW + n * SBW + kp] = *reinterpret_cast<uint32_t*>(&lp);
    }

    // --- Edge scatter: one edge per warp; lane owns 4 contiguous dims ---
    int e = blockIdx.x * (blockDim.x >> 5) + (threadIdx.x >> 5);
    if (e >= E) return;
    int lane = threadIdx.x & 31;

    int s  = __ldg(src + e);
    int d  = __ldg(dst + e);
    int i0 = __ldg(eidx + e * NF_DIM + 0);
    int i1 = __ldg(eidx + e * NF_DIM + 1);
    int i2 = __ldg(eidx + e * NF_DIM + 2);

    int c = lane * 4;
    float4 v  = __ldg(reinterpret_cast<const float4*>(nfeat + (size_t)s * D_DIM + c));
    float4 e0 = __ldg(reinterpret_cast<const float4*>(emb + ((0 * V_DIM + i0) * D_DIM) + c));
    float4 e1 = __ldg(reinterpret_cast<const float4*>(emb + ((1 * V_DIM + i1) * D_DIM) + c));
    float4 e2 = __ldg(reinterpret_cast<const float4*>(emb + ((2 * V_DIM + i2) * D_DIM) + c));

    float mx = v.x + e0.x + e1.x + e2.x;
    float my = v.y + e0.y + e1.y + e2.y;
    float mz = v.z + e0.z + e1.z + e2.z;
    float mw = v.w + e0.w + e1.w + e2.w;

    float* p = g_acc + (size_t)d * D_DIM + c;
    asm volatile("red.global.add.v4.f32 [%0], {%1, %2, %3, %4};"
                 :: "l"(p), "f"(mx), "f"(my), "f"(mz), "f"(mw) : "memory");

    if (lane == 0) {
        atomicAdd(&g_deg[d], 1.0f);
    }
}

// ---------------------------------------------------------------------------
// K1b: g_deg[i] -> 1/(g_deg[i]+1)
// ---------------------------------------------------------------------------
__global__ void invd_kernel(int N) {
    int i = blockIdx.x * blockDim.x + threadIdx.x;
    if (i < N) g_deg[i] = 1.0f / (g_deg[i] + 1.0f);
}

// ---------------------------------------------------------------------------
// K2: PERSISTENT PIPELINED bf16x3 GEMM. grid=148 x 512 (16 warps, 1 CTA/SM).
//     64-row tiles, double-buffered H smem, register prefetch of next tile.
//     g_acc is pre-seeded with nfeat, so H = g_acc * g_deg (single stream!).
// ---------------------------------------------------------------------------
#define HBUF_WORDS (64 * SBW)

__global__ void __launch_bounds__(512, 1)
gemm_bf16_kernel(const float* __restrict__ b,
                 float* __restrict__ out, int N, int numTiles) {
    extern __shared__ uint32_t smu[];
    uint32_t* Wth = smu;                        // 128*68
    uint32_t* Wtl = Wth + D_DIM * SBW;          // 128*68
    uint32_t* Hbuf = Wtl + D_DIM * SBW;         // 4 * 64*68
    float* bs = reinterpret_cast<float*>(Hbuf + 4 * HBUF_WORDS);  // 128

    int tid = threadIdx.x;

    // Prologue: stage packed W (pure uint4 copy) + bias
    {
        const uint4* src4 = reinterpret_cast<const uint4*>(g_Wpk);
        uint4* dst4 = reinterpret_cast<uint4*>(smu);
        #pragma unroll
        for (int i = tid; i < (2 * D_DIM * SBW) / 4; i += 512)
            dst4[i] = src4[i];
        if (tid < D_DIM) bs[tid] = __ldg(b + tid);
    }

    // Staging geometry: row = tid>>3, q = tid&7; thread covers float4 cols q*4..q*4+3.
    int srow = tid >> 3;
    int q = tid & 7;
    const float4* ac4 = reinterpret_cast<const float4*>(g_acc);

    int wid = tid >> 5;
    int lane = tid & 31;
    int gid = lane >> 2;
    int tig = lane & 3;
    int wr = (wid >> 2) * 16;   // warp grid 4x4; warp tile 16 rows x 32 cols
    int wc = (wid & 3) * 32;

    int tile = blockIdx.x;

    // Prefetch first tile into registers (single stream: g_acc only)
    float4 pa[4];
    float pinvd = 0.f;
    {
        int row = tile * 64 + srow;
        bool ok = (row < N);
        pinvd = ok ? g_deg[row] : 0.f;
        #pragma unroll
        for (int j = 0; j < 4; j++)
            pa[j] = ok ? *(ac4 + (size_t)row * 32 + q * 4 + j)
                       : make_float4(0.f, 0.f, 0.f, 0.f);
    }

    int cur = 0;
    while (tile < numTiles) {
        int row0 = tile * 64;
        uint32_t* Hh = Hbuf + cur * (2 * HBUF_WORDS);
        uint32_t* Hl = Hh + HBUF_WORDS;

        // Convert prefetched registers -> smem (truncation hi split + bf16 lo)
        {
            #pragma unroll
            for (int j = 0; j < 4; j++) {
                float x0 = pa[j].x * pinvd;
                float x1 = pa[j].y * pinvd;
                float x2 = pa[j].z * pinvd;
                float x3 = pa[j].w * pinvd;
                uint32_t b0 = __float_as_uint(x0), b1 = __float_as_uint(x1);
                uint32_t b2 = __float_as_uint(x2), b3 = __float_as_uint(x3);
                uint32_t hp0, hp1;
                asm("prmt.b32 %0, %1, %2, 0x7632;" : "=r"(hp0) : "r"(b0), "r"(b1));
                asm("prmt.b32 %0, %1, %2, 0x7632;" : "=r"(hp1) : "r"(b2), "r"(b3));
                float l0 = x0 - __uint_as_float(b0 & 0xFFFF0000u);
                float l1 = x1 - __uint_as_float(b1 & 0xFFFF0000u);
                float l2 = x2 - __uint_as_float(b2 & 0xFFFF0000u);
                float l3 = x3 - __uint_as_float(b3 & 0xFFFF0000u);
                __nv_bfloat162 lp0 = __floats2bfloat162_rn(l0, l1);
                __nv_bfloat162 lp1 = __floats2bfloat162_rn(l2, l3);
                int base = srow * SBW + (q * 4 + j) * 2;
                Hh[base]     = hp0;
                Hh[base + 1] = hp1;
                Hl[base]     = *reinterpret_cast<uint32_t*>(&lp0);
                Hl[base + 1] = *reinterpret_cast<uint32_t*>(&lp1);
            }
        }
        __syncthreads();

        // Issue prefetch for next tile (latency hides under mainloop)
        int ntile = tile + gridDim.x;
        if (ntile < numTiles) {
            int row = ntile * 64 + srow;
            bool ok = (row < N);
            pinvd = ok ? g_deg[row] : 0.f;
            #pragma unroll
            for (int j = 0; j < 4; j++)
                pa[j] = ok ? *(ac4 + (size_t)row * 32 + q * 4 + j)
                           : make_float4(0.f, 0.f, 0.f, 0.f);
        }

        // Mainloop: warp tile 16 rows x 32 cols (4 n-tiles)
        float c[4][4];
        #pragma unroll
        for (int nt = 0; nt < 4; nt++)
            #pragma unroll
            for (int r = 0; r < 4; r++) c[nt][r] = 0.f;

        #pragma unroll
        for (int kw = 0; kw < 64; kw += 8) {   // K chunk = 16
            uint32_t ah[4], al[4];
            {
                int r = wr + gid;
                ah[0] = Hh[r * SBW + kw + tig];
                ah[1] = Hh[(r + 8) * SBW + kw + tig];
                ah[2] = Hh[r * SBW + kw + 4 + tig];
                ah[3] = Hh[(r + 8) * SBW + kw + 4 + tig];
                al[0] = Hl[r * SBW + kw + tig];
                al[1] = Hl[(r + 8) * SBW + kw + tig];
                al[2] = Hl[r * SBW + kw + 4 + tig];
                al[3] = Hl[(r + 8) * SBW + kw + 4 + tig];
            }
            uint32_t bh[4][2], bl[4][2];
            #pragma unroll
            for (int nt = 0; nt < 4; nt++) {
                int n = wc + nt * 8 + gid;
                bh[nt][0] = Wth[n * SBW + kw + tig];
                bh[nt][1] = Wth[n * SBW + kw + 4 + tig];
                bl[nt][0] = Wtl[n * SBW + kw + tig];
                bl[nt][1] = Wtl[n * SBW + kw + 4 + tig];
            }
            #define MMA16(CR, A, B)                                              \
                asm volatile(                                                    \
                    "mma.sync.aligned.m16n8k16.row.col.f32.bf16.bf16.f32 "       \
                    "{%0,%1,%2,%3}, {%4,%5,%6,%7}, {%8,%9}, {%0,%1,%2,%3};"      \
                    : "+f"((CR)[0]), "+f"((CR)[1]),                              \
                      "+f"((CR)[2]), "+f"((CR)[3])                               \
                    : "r"(A[0]), "r"(A[1]), "r"(A[2]), "r"(A[3]),                \
                      "r"(B[0]), "r"(B[1]))
            #pragma unroll
            for (int nt = 0; nt < 4; nt++) MMA16(c[nt], ah, bh[nt]);
            #pragma unroll
            for (int nt = 0; nt < 4; nt++) MMA16(c[nt], al, bh[nt]);
            #pragma unroll
            for (int nt = 0; nt < 4; nt++) MMA16(c[nt], ah, bl[nt]);
            #undef MMA16
        }

        // Epilogue: bias + store
        #pragma unroll
        for (int nt = 0; nt < 4; nt++) {
            int col = wc + nt * 8 + 2 * tig;
            float bx = bs[col], by = bs[col + 1];
            int r_top = row0 + wr + gid;
            if (r_top < N) {
                float2 o = make_float2(c[nt][0] + bx, c[nt][1] + by);
                *reinterpret_cast<float2*>(out + (size_t)r_top * D_DIM + col) = o;
            }
            int r_bot = r_top + 8;
            if (r_bot < N) {
                float2 o = make_float2(c[nt][2] + bx, c[nt][3] + by);
                *reinterpret_cast<float2*>(out + (size_t)r_bot * D_DIM + col) = o;
            }
        }

        tile = ntile;
        cur ^= 1;
        __syncthreads();  // buffer reads done before refill
    }
}

// ---------------------------------------------------------------------------
// Launch
// Inputs: nfeat[N*D] f32, src[E] i32, dst[E] i32, efeat_idx[E*3] i32,
//         edge_emb[3*8*128] f32, W[128*128] f32, b[128] f32 -> out float[N*128]
// ---------------------------------------------------------------------------
extern "C" void kernel_launch(void* const* d_in, const int* in_sizes, int n_in,
                              void* d_out, int out_size) {
    const float* nfeat = (const float*)d_in[0];
    const int*   src   = (const int*)d_in[1];
    const int*   dst   = (const int*)d_in[2];
    const int*   eidx  = (const int*)d_in[3];
    const float* emb   = (const float*)d_in[4];
    const float* W     = (const float*)d_in[5];
    const float* b     = (const float*)d_in[6];
    float* out = (float*)d_out;

    int N = in_sizes[0] / D_DIM;
    int E = in_sizes[1];

    // Seed accumulator with nfeat (D2D copy, graph-capturable); zero degrees.
    void* acc_ptr = nullptr;
    void* deg_ptr = nullptr;
    cudaGetSymbolAddress(&acc_ptr, g_acc);
    cudaGetSymbolAddress(&deg_ptr, g_deg);
    cudaMemcpyAsync(acc_ptr, nfeat, (size_t)N * D_DIM * sizeof(float),
                    cudaMemcpyDeviceToDevice);
    cudaMemsetAsync(deg_ptr, 0, (size_t)N * sizeof(float));

    // Edge scatter (one edge per warp) + folded W packing
    edge_scatter_kernel<<<(E + 7) / 8, 256>>>(nfeat, src, dst, eidx, emb, W, E);

    // deg -> 1/(deg+1)
    invd_kernel<<<(N + 511) / 512, 512>>>(N);

    // Persistent pipelined GEMM (reads only g_acc)
    int numTiles = (N + 63) / 64;
    int smem = (2 * D_DIM * SBW + 4 * HBUF_WORDS + 128) * 4;  // 139,776 B
    cudaFuncSetAttribute(gemm_bf16_kernel, cudaFuncAttributeMaxDynamicSharedMemorySize, smem);
    gemm_bf16_kernel<<<148, 512, smem>>>(b, out, N, numTiles);
}